// round 5
// baseline (speedup 1.0000x reference)
#include <cuda_runtime.h>
#include <cuda_bf16.h>

// Problem constants (fixed by the reference)
#define NUM_TASKS 1000
#define N_FEAT    256
#define HID       128
#define BATCH_MAX 4096
#define RCMAX     8      // max rows per W1 streaming pass

// Scratch (static __device__ globals — allowed; no runtime allocation)
__device__ int g_offs[NUM_TASKS + 1];
__device__ int g_rows[BATCH_MAX];
__device__ int g_order[NUM_TASKS];
__device__ int g_cursor;

// ---------------------------------------------------------------------------
// Setup: histogram -> warp-shuffle scan -> CSR scatter -> counting sort of
// tasks by descending row count -> reset work cursor. One CTA, few syncs.
// ---------------------------------------------------------------------------
__global__ __launch_bounds__(1024, 1)
void setup_kernel(const int* __restrict__ task_ids, int batch) {
    __shared__ int cnt[1024];
    __shared__ int wsum[32];
    __shared__ int ccnt[32];
    __shared__ int ccur[32];

    int tid  = threadIdx.x;
    int lane = tid & 31;
    int wid  = tid >> 5;

    cnt[tid] = 0;
    if (tid < 32) ccnt[tid] = 0;
    __syncthreads();

    for (int i = tid; i < batch; i += 1024)
        atomicAdd(&cnt[task_ids[i]], 1);
    __syncthreads();

    int mycount = cnt[tid];

    // warp-level inclusive scan
    int v = mycount;
    #pragma unroll
    for (int off = 1; off < 32; off <<= 1) {
        int u = __shfl_up_sync(0xffffffffu, v, off);
        if (lane >= off) v += u;
    }
    if (lane == 31) wsum[wid] = v;
    __syncthreads();
    if (wid == 0) {
        int w = wsum[lane];
        #pragma unroll
        for (int off = 1; off < 32; off <<= 1) {
            int u = __shfl_up_sync(0xffffffffu, w, off);
            if (lane >= off) w += u;
        }
        wsum[lane] = w;
    }
    __syncthreads();
    int incl = v + (wid > 0 ? wsum[wid - 1] : 0);

    if (tid == 0) { g_offs[0] = 0; g_cursor = 0; }
    if (tid < NUM_TASKS) g_offs[tid + 1] = incl;

    int excl = incl - mycount;
    __syncthreads();
    cnt[tid] = excl;               // cursors for scatter
    __syncthreads();

    for (int i = tid; i < batch; i += 1024) {
        int t = task_ids[i];
        int pos = atomicAdd(&cnt[t], 1);
        g_rows[pos] = i;
    }

    // counting sort of tasks by descending n (clamped to 31)
    int cls = 31;
    if (tid < NUM_TASKS) {
        cls = 31 - min(mycount, 31);
        atomicAdd(&ccnt[cls], 1);
    }
    __syncthreads();
    if (wid == 0) {
        int c = ccnt[lane];
        #pragma unroll
        for (int off = 1; off < 32; off <<= 1) {
            int u = __shfl_up_sync(0xffffffffu, c, off);
            if (lane >= off) c += u;
        }
        ccur[lane] = c - ccnt[lane];   // exclusive
    }
    __syncthreads();
    if (tid < NUM_TASKS) {
        int pos = atomicAdd(&ccur[cls], 1);
        g_order[pos] = tid;
    }
}

// ---------------------------------------------------------------------------
// One W1 streaming pass for R rows. AHEAD = prefetch distance in batches
// (batch = 4 float4/thread). tid in [0,128): q=tid&31 (h-quad), p=tid>>5
// (f-phase warp). Iteration i reads contiguous 2KB stripe Wv[i*128+tid].
// The first AHEAD W1 batches are issued BEFORE the x staging + barrier so
// the stream never drains at pass boundaries.
// ---------------------------------------------------------------------------
template<int R, int AHEAD>
__device__ __forceinline__
void stream_pass(const float4* __restrict__ Wv,
                 const float* __restrict__ x,
                 const float* __restrict__ b1s,
                 const float* __restrict__ w2s,
                 float b2,
                 float (*xs)[N_FEAT],
                 float (*red)[RCMAX][HID],
                 const int* __restrict__ rowp,
                 int nr,
                 float* __restrict__ out,
                 int tid, int q, int p) {
    // hoisted W1 prefetch: in flight while x rows are gathered below
    float4 buf[AHEAD][4];
    #pragma unroll
    for (int a = 0; a < AHEAD; ++a)
        #pragma unroll
        for (int j = 0; j < 4; ++j)
            buf[a][j] = Wv[(a * 4 + j) * 128 + tid];

    // stage x rows into smem (zero-fill unused rows)
    #pragma unroll
    for (int r = 0; r < R; ++r) {
        float v0 = 0.f, v1 = 0.f;
        if (r < nr) {
            int row = rowp[r];
            v0 = x[(size_t)row * N_FEAT + tid];
            v1 = x[(size_t)row * N_FEAT + 128 + tid];
        }
        xs[r][tid]       = v0;
        xs[r][128 + tid] = v1;
    }
    __syncthreads();

    float4 acc[R];
    #pragma unroll
    for (int r = 0; r < R; ++r) acc[r] = make_float4(0.f, 0.f, 0.f, 0.f);

    // pipelined mainloop: 16 batches of 4 float4, AHEAD batches in flight
    #pragma unroll
    for (int ib = 0; ib < 16; ++ib) {
        float4 nb[4];
        if (ib + AHEAD < 16) {
            #pragma unroll
            for (int j = 0; j < 4; ++j)
                nb[j] = Wv[((ib + AHEAD) * 4 + j) * 128 + tid];
        }
        #pragma unroll
        for (int j = 0; j < 4; ++j) {
            float4 w4 = buf[ib % AHEAD][j];
            int f = (ib * 4 + j) * 4 + p;
            #pragma unroll
            for (int r = 0; r < R; ++r) {
                float xv = xs[r][f];          // warp-uniform smem broadcast
                acc[r].x = fmaf(xv, w4.x, acc[r].x);
                acc[r].y = fmaf(xv, w4.y, acc[r].y);
                acc[r].z = fmaf(xv, w4.z, acc[r].z);
                acc[r].w = fmaf(xv, w4.w, acc[r].w);
            }
        }
        if (ib + AHEAD < 16) {
            #pragma unroll
            for (int j = 0; j < 4; ++j) buf[ib % AHEAD][j] = nb[j];
        }
    }

    // cross-phase reduction staging
    #pragma unroll
    for (int r = 0; r < R; ++r)
        ((float4*)&red[p][r][0])[q] = acc[r];
    __syncthreads();

    // epilogue: warp p handles rows p, p+4, ...; lane q strides H by 32
    for (int rr = p; rr < nr; rr += 4) {
        float part = 0.f;
        #pragma unroll
        for (int hh = q; hh < HID; hh += 32) {
            float s = red[0][rr][hh] + red[1][rr][hh] +
                      red[2][rr][hh] + red[3][rr][hh] + b1s[hh];
            // exact-erf GELU
            float g = 0.5f * s * (1.0f + erff(s * 0.70710678118654752f));
            part = fmaf(g, w2s[hh], part);
        }
        #pragma unroll
        for (int off = 16; off > 0; off >>= 1)
            part += __shfl_down_sync(0xffffffffu, part, off);
        if (q == 0)
            out[rowp[rr]] = part + b2;
    }
    __syncthreads();   // protect xs/red for next pass
}

// ---------------------------------------------------------------------------
// Main: persistent CTAs pull tasks (descending size) from a global cursor.
// Grid = 4 CTAs/SM * 148 SMs; no wave-boundary or tail imbalance.
// ---------------------------------------------------------------------------
__global__ __launch_bounds__(128, 4)
void main_kernel(const float* __restrict__ x,
                 const float* __restrict__ l1_emb,
                 const float* __restrict__ l1_bias,
                 const float* __restrict__ l2_emb,
                 const float* __restrict__ l2_bias,
                 float* __restrict__ out) {
    __shared__ float xs[RCMAX][N_FEAT];       // 8 KB
    __shared__ float red[4][RCMAX][HID];      // 16 KB
    __shared__ float b1s[HID], w2s[HID];
    __shared__ int s_idx;

    int tid = threadIdx.x;
    int q = tid & 31;
    int p = tid >> 5;

    for (;;) {
        if (tid == 0) s_idx = atomicAdd(&g_cursor, 1);
        __syncthreads();
        int idx = s_idx;
        __syncthreads();
        if (idx >= NUM_TASKS) break;

        int t = g_order[idx];
        int start = g_offs[t];
        int n     = g_offs[t + 1] - start;
        if (n == 0) continue;

        b1s[tid] = l1_bias[t * HID + tid];
        w2s[tid] = l2_emb[t * HID + tid];
        float b2 = l2_bias[t];
        __syncthreads();

        const float4* __restrict__ Wv =
            (const float4*)(l1_emb + (size_t)t * (N_FEAT * HID));

        for (int r0 = 0; r0 < n; r0 += RCMAX) {
            int nr = min(RCMAX, n - r0);
            const int* rowp = g_rows + start + r0;
            if (nr <= 1)
                stream_pass<1, 3>(Wv, x, b1s, w2s, b2, xs, red, rowp, nr, out, tid, q, p);
            else if (nr <= 2)
                stream_pass<2, 3>(Wv, x, b1s, w2s, b2, xs, red, rowp, nr, out, tid, q, p);
            else if (nr <= 4)
                stream_pass<4, 2>(Wv, x, b1s, w2s, b2, xs, red, rowp, nr, out, tid, q, p);
            else
                stream_pass<8, 1>(Wv, x, b1s, w2s, b2, xs, red, rowp, nr, out, tid, q, p);
        }
    }
}

extern "C" void kernel_launch(void* const* d_in, const int* in_sizes, int n_in,
                              void* d_out, int out_size) {
    const float* x        = (const float*)d_in[0];
    const int*   task_ids = (const int*)  d_in[1];
    const float* l1_emb   = (const float*)d_in[2];
    const float* l1_bias  = (const float*)d_in[3];
    const float* l2_emb   = (const float*)d_in[4];
    const float* l2_bias  = (const float*)d_in[5];
    float* out = (float*)d_out;

    int batch = in_sizes[1];   // 4096

    setup_kernel<<<1, 1024>>>(task_ids, batch);
    main_kernel<<<4 * 148, 128>>>(x, l1_emb, l1_bias, l2_emb, l2_bias, out);
}

// round 10
// speedup vs baseline: 1.0086x; 1.0086x over previous
#include <cuda_runtime.h>
#include <cuda_bf16.h>
#include <cstdint>

// Problem constants (fixed by the reference)
#define NUM_TASKS 1000
#define N_FEAT    256
#define HID       128
#define BATCH_MAX 4096
#define RCMAX     8      // max rows per W1 streaming pass
#define NSLOT     4      // smem ring slots
#define NBATCH    32     // batches per pass (batch = 2 stripes = 4KB CTA-wide)

// Scratch (static __device__ globals — allowed; no runtime allocation)
__device__ int g_offs[NUM_TASKS + 1];
__device__ int g_rows[BATCH_MAX];
__device__ int g_order[NUM_TASKS];
__device__ int g_cursor;

// ---------------------------------------------------------------------------
// cp.async helpers (.cg = bypass L1; W1 is a single-use stream)
// ---------------------------------------------------------------------------
__device__ __forceinline__ void cp_async16(void* smem_dst, const void* gmem_src) {
    uint32_t a = (uint32_t)__cvta_generic_to_shared(smem_dst);
    asm volatile("cp.async.cg.shared.global [%0], [%1], 16;\n"
                 :: "r"(a), "l"(gmem_src));
}
__device__ __forceinline__ void cp_commit() {
    asm volatile("cp.async.commit_group;\n" ::: "memory");
}
template<int N>
__device__ __forceinline__ void cp_wait() {
    asm volatile("cp.async.wait_group %0;\n" :: "n"(N) : "memory");
}

// ---------------------------------------------------------------------------
// Setup: histogram -> warp-shuffle scan -> CSR scatter -> counting sort of
// tasks by descending row count -> reset work cursor. One CTA, few syncs.
// ---------------------------------------------------------------------------
__global__ __launch_bounds__(1024, 1)
void setup_kernel(const int* __restrict__ task_ids, int batch) {
    __shared__ int cnt[1024];
    __shared__ int wsum[32];
    __shared__ int ccnt[32];
    __shared__ int ccur[32];

    int tid  = threadIdx.x;
    int lane = tid & 31;
    int wid  = tid >> 5;

    cnt[tid] = 0;
    if (tid < 32) ccnt[tid] = 0;
    __syncthreads();

    for (int i = tid; i < batch; i += 1024)
        atomicAdd(&cnt[task_ids[i]], 1);
    __syncthreads();

    int mycount = cnt[tid];

    // warp-level inclusive scan
    int v = mycount;
    #pragma unroll
    for (int off = 1; off < 32; off <<= 1) {
        int u = __shfl_up_sync(0xffffffffu, v, off);
        if (lane >= off) v += u;
    }
    if (lane == 31) wsum[wid] = v;
    __syncthreads();
    if (wid == 0) {
        int w = wsum[lane];
        #pragma unroll
        for (int off = 1; off < 32; off <<= 1) {
            int u = __shfl_up_sync(0xffffffffu, w, off);
            if (lane >= off) w += u;
        }
        wsum[lane] = w;
    }
    __syncthreads();
    int incl = v + (wid > 0 ? wsum[wid - 1] : 0);

    if (tid == 0) { g_offs[0] = 0; g_cursor = 0; }
    if (tid < NUM_TASKS) g_offs[tid + 1] = incl;

    int excl = incl - mycount;
    __syncthreads();
    cnt[tid] = excl;               // cursors for scatter
    __syncthreads();

    for (int i = tid; i < batch; i += 1024) {
        int t = task_ids[i];
        int pos = atomicAdd(&cnt[t], 1);
        g_rows[pos] = i;
    }

    // counting sort of tasks by descending n (clamped to 31)
    int cls = 31;
    if (tid < NUM_TASKS) {
        cls = 31 - min(mycount, 31);
        atomicAdd(&ccnt[cls], 1);
    }
    __syncthreads();
    if (wid == 0) {
        int c = ccnt[lane];
        #pragma unroll
        for (int off = 1; off < 32; off <<= 1) {
            int u = __shfl_up_sync(0xffffffffu, c, off);
            if (lane >= off) c += u;
        }
        ccur[lane] = c - ccnt[lane];   // exclusive
    }
    __syncthreads();
    if (tid < NUM_TASKS) {
        int pos = atomicAdd(&ccur[cls], 1);
        g_order[pos] = tid;
    }
}

// ---------------------------------------------------------------------------
// One W1 streaming pass for R rows, cp.async smem ring (depth 4, 3 groups
// in flight). Batch b covers stripes i=2b,2b+1; thread tid owns float4
// [i*128+tid]; warp p handles f = i*4+p, lane q the h-quad [4q..4q+3].
// Ring slots are strictly per-thread (each thread writes & reads only its
// own element), so no barriers are needed on the ring. WAR on slot reuse is
// safe: the LDS of a slot completes (in-thread program order) before the
// cp.async that overwrites it is issued.
// ---------------------------------------------------------------------------
template<int R>
__device__ __forceinline__
void stream_pass(const float4* __restrict__ Wv,
                 const float* __restrict__ x,
                 const float* __restrict__ b1s,
                 const float* __restrict__ w2s,
                 float b2,
                 float4 (*ring)[2][128],
                 float (*xs)[N_FEAT],
                 float (*red)[RCMAX][HID],
                 const int* __restrict__ rowp,
                 int nr,
                 float* __restrict__ out,
                 int tid, int q, int p) {
    // prologue: fire batches 0..2 before x staging (depth lives in smem,
    // not registers; stream is in flight during the x gather + barrier)
    #pragma unroll
    for (int b = 0; b < NSLOT - 1; ++b) {
        #pragma unroll
        for (int j = 0; j < 2; ++j)
            cp_async16(&ring[b][j][tid], Wv + ((2 * b + j) * 128 + tid));
        cp_commit();
    }

    // stage x rows into smem (zero-fill unused rows)
    #pragma unroll
    for (int r = 0; r < R; ++r) {
        float v0 = 0.f, v1 = 0.f;
        if (r < nr) {
            int row = rowp[r];
            v0 = x[(size_t)row * N_FEAT + tid];
            v1 = x[(size_t)row * N_FEAT + 128 + tid];
        }
        xs[r][tid]       = v0;
        xs[r][128 + tid] = v1;
    }
    __syncthreads();

    float4 acc[R];
    #pragma unroll
    for (int r = 0; r < R; ++r) acc[r] = make_float4(0.f, 0.f, 0.f, 0.f);

    // steady state: consume batch ib, issue batch ib+3
    // (unroll 2 keeps hot code for all 4 template instantiations inside L0)
    #pragma unroll 2
    for (int ib = 0; ib < NBATCH - 3; ++ib) {
        cp_wait<2>();                     // <=2 pending => slot ib landed
        #pragma unroll
        for (int j = 0; j < 2; ++j) {
            float4 w4 = ring[ib & (NSLOT - 1)][j][tid];
            int f = (2 * ib + j) * 4 + p;
            #pragma unroll
            for (int r = 0; r < R; ++r) {
                float xv = xs[r][f];          // warp-uniform smem broadcast
                acc[r].x = fmaf(xv, w4.x, acc[r].x);
                acc[r].y = fmaf(xv, w4.y, acc[r].y);
                acc[r].z = fmaf(xv, w4.z, acc[r].z);
                acc[r].w = fmaf(xv, w4.w, acc[r].w);
            }
        }
        int nb = ib + 3;
        #pragma unroll
        for (int j = 0; j < 2; ++j)
            cp_async16(&ring[nb & (NSLOT - 1)][j][tid], Wv + ((2 * nb + j) * 128 + tid));
        cp_commit();
    }

    // drain tail batches 29,30,31 with exact wait counts
    #pragma unroll
    for (int k = 0; k < 3; ++k) {
        int ib = NBATCH - 3 + k;
        if (k == 0) cp_wait<2>();
        else if (k == 1) cp_wait<1>();
        else cp_wait<0>();
        #pragma unroll
        for (int j = 0; j < 2; ++j) {
            float4 w4 = ring[ib & (NSLOT - 1)][j][tid];
            int f = (2 * ib + j) * 4 + p;
            #pragma unroll
            for (int r = 0; r < R; ++r) {
                float xv = xs[r][f];
                acc[r].x = fmaf(xv, w4.x, acc[r].x);
                acc[r].y = fmaf(xv, w4.y, acc[r].y);
                acc[r].z = fmaf(xv, w4.z, acc[r].z);
                acc[r].w = fmaf(xv, w4.w, acc[r].w);
            }
        }
    }

    // cross-phase reduction staging
    #pragma unroll
    for (int r = 0; r < R; ++r)
        ((float4*)&red[p][r][0])[q] = acc[r];
    __syncthreads();

    // epilogue: warp p handles rows p, p+4, ...; lane q strides H by 32
    for (int rr = p; rr < nr; rr += 4) {
        float part = 0.f;
        #pragma unroll
        for (int hh = q; hh < HID; hh += 32) {
            float s = red[0][rr][hh] + red[1][rr][hh] +
                      red[2][rr][hh] + red[3][rr][hh] + b1s[hh];
            // exact-erf GELU
            float g = 0.5f * s * (1.0f + erff(s * 0.70710678118654752f));
            part = fmaf(g, w2s[hh], part);
        }
        #pragma unroll
        for (int off = 16; off > 0; off >>= 1)
            part += __shfl_down_sync(0xffffffffu, part, off);
        if (q == 0)
            out[rowp[rr]] = part + b2;
    }
    __syncthreads();   // protect xs/red for next pass
}

// ---------------------------------------------------------------------------
// Main: persistent CTAs pull tasks (descending size) from a global cursor.
// 5 CTAs/SM; 41KB smem/CTA (205KB/SM < 228KB carveout).
// ---------------------------------------------------------------------------
__global__ __launch_bounds__(128, 5)
void main_kernel(const float* __restrict__ x,
                 const float* __restrict__ l1_emb,
                 const float* __restrict__ l1_bias,
                 const float* __restrict__ l2_emb,
                 const float* __restrict__ l2_bias,
                 float* __restrict__ out) {
    __shared__ float4 ring[NSLOT][2][128];    // 16 KB cp.async ring
    __shared__ float xs[RCMAX][N_FEAT];       // 8 KB
    __shared__ float red[4][RCMAX][HID];      // 16 KB
    __shared__ float b1s[HID], w2s[HID];
    __shared__ int s_idx;

    int tid = threadIdx.x;
    int q = tid & 31;
    int p = tid >> 5;

    for (;;) {
        if (tid == 0) s_idx = atomicAdd(&g_cursor, 1);
        __syncthreads();
        int idx = s_idx;
        __syncthreads();
        if (idx >= NUM_TASKS) break;

        int t = g_order[idx];
        int start = g_offs[t];
        int n     = g_offs[t + 1] - start;
        if (n == 0) continue;

        b1s[tid] = l1_bias[t * HID + tid];
        w2s[tid] = l2_emb[t * HID + tid];
        float b2 = l2_bias[t];
        __syncthreads();

        const float4* __restrict__ Wv =
            (const float4*)(l1_emb + (size_t)t * (N_FEAT * HID));

        for (int r0 = 0; r0 < n; r0 += RCMAX) {
            int nr = min(RCMAX, n - r0);
            const int* rowp = g_rows + start + r0;
            if (nr <= 1)
                stream_pass<1>(Wv, x, b1s, w2s, b2, ring, xs, red, rowp, nr, out, tid, q, p);
            else if (nr <= 2)
                stream_pass<2>(Wv, x, b1s, w2s, b2, ring, xs, red, rowp, nr, out, tid, q, p);
            else if (nr <= 4)
                stream_pass<4>(Wv, x, b1s, w2s, b2, ring, xs, red, rowp, nr, out, tid, q, p);
            else
                stream_pass<8>(Wv, x, b1s, w2s, b2, ring, xs, red, rowp, nr, out, tid, q, p);
        }
    }
}

extern "C" void kernel_launch(void* const* d_in, const int* in_sizes, int n_in,
                              void* d_out, int out_size) {
    const float* x        = (const float*)d_in[0];
    const int*   task_ids = (const int*)  d_in[1];
    const float* l1_emb   = (const float*)d_in[2];
    const float* l1_bias  = (const float*)d_in[3];
    const float* l2_emb   = (const float*)d_in[4];
    const float* l2_bias  = (const float*)d_in[5];
    float* out = (float*)d_out;

    int batch = in_sizes[1];   // 4096

    setup_kernel<<<1, 1024>>>(task_ids, batch);
    main_kernel<<<5 * 148, 128>>>(x, l1_emb, l1_bias, l2_emb, l2_bias, out);
}

// round 11
// speedup vs baseline: 1.0888x; 1.0796x over previous
#include <cuda_runtime.h>
#include <cuda_bf16.h>
#include <cstdint>

// Problem constants (fixed by the reference)
#define NUM_TASKS 1000
#define N_FEAT    256
#define HID       128
#define BATCH_MAX 4096
#define RCMAX     8      // max rows per W1 streaming pass
#define NSLOT     4      // TMA ring slots
#define NCHUNK    16     // chunks per pass: 16 x 8KB = 128KB
#define CHUNK_B   8192u

// Scratch (static __device__ globals — allowed; no runtime allocation)
__device__ int g_offs[NUM_TASKS + 1];
__device__ int g_rows[BATCH_MAX];
__device__ int g_order[NUM_TASKS];
__device__ int g_cursor;

// ---------------------------------------------------------------------------
// mbarrier + TMA bulk helpers
// ---------------------------------------------------------------------------
__device__ __forceinline__ void mbar_init(uint32_t a, uint32_t cnt) {
    asm volatile("mbarrier.init.shared.b64 [%0], %1;" :: "r"(a), "r"(cnt) : "memory");
}
__device__ __forceinline__ void mbar_expect_tx(uint32_t a, uint32_t bytes) {
    asm volatile("mbarrier.arrive.expect_tx.shared.b64 _, [%0], %1;"
                 :: "r"(a), "r"(bytes) : "memory");
}
__device__ __forceinline__ void mbar_wait(uint32_t a, uint32_t parity) {
    asm volatile(
        "{\n\t"
        ".reg .pred P1;\n\t"
        "WL_%=:\n\t"
        "mbarrier.try_wait.parity.acquire.cta.shared::cta.b64 P1, [%0], %1, 0x989680;\n\t"
        "@P1 bra.uni WD_%=;\n\t"
        "bra.uni WL_%=;\n\t"
        "WD_%=:\n\t"
        "}"
        :: "r"(a), "r"(parity) : "memory");
}
__device__ __forceinline__ void bulk_g2s(uint32_t smem_dst, const void* gmem_src,
                                         uint32_t bytes, uint32_t mbar) {
    asm volatile(
        "cp.async.bulk.shared::cta.global.mbarrier::complete_tx::bytes [%0], [%1], %2, [%3];"
        :: "r"(smem_dst), "l"(gmem_src), "r"(bytes), "r"(mbar) : "memory");
}

// ---------------------------------------------------------------------------
// Setup: histogram -> warp-shuffle scan -> CSR scatter -> counting sort of
// tasks by descending row count -> reset work cursor. One CTA, few syncs.
// ---------------------------------------------------------------------------
__global__ __launch_bounds__(1024, 1)
void setup_kernel(const int* __restrict__ task_ids, int batch) {
    __shared__ int cnt[1024];
    __shared__ int wsum[32];
    __shared__ int ccnt[32];
    __shared__ int ccur[32];

    int tid  = threadIdx.x;
    int lane = tid & 31;
    int wid  = tid >> 5;

    cnt[tid] = 0;
    if (tid < 32) ccnt[tid] = 0;
    __syncthreads();

    for (int i = tid; i < batch; i += 1024)
        atomicAdd(&cnt[task_ids[i]], 1);
    __syncthreads();

    int mycount = cnt[tid];

    int v = mycount;
    #pragma unroll
    for (int off = 1; off < 32; off <<= 1) {
        int u = __shfl_up_sync(0xffffffffu, v, off);
        if (lane >= off) v += u;
    }
    if (lane == 31) wsum[wid] = v;
    __syncthreads();
    if (wid == 0) {
        int w = wsum[lane];
        #pragma unroll
        for (int off = 1; off < 32; off <<= 1) {
            int u = __shfl_up_sync(0xffffffffu, w, off);
            if (lane >= off) w += u;
        }
        wsum[lane] = w;
    }
    __syncthreads();
    int incl = v + (wid > 0 ? wsum[wid - 1] : 0);

    if (tid == 0) { g_offs[0] = 0; g_cursor = 0; }
    if (tid < NUM_TASKS) g_offs[tid + 1] = incl;

    int excl = incl - mycount;
    __syncthreads();
    cnt[tid] = excl;
    __syncthreads();

    for (int i = tid; i < batch; i += 1024) {
        int t = task_ids[i];
        int pos = atomicAdd(&cnt[t], 1);
        g_rows[pos] = i;
    }

    int cls = 31;
    if (tid < NUM_TASKS) {
        cls = 31 - min(mycount, 31);
        atomicAdd(&ccnt[cls], 1);
    }
    __syncthreads();
    if (wid == 0) {
        int c = ccnt[lane];
        #pragma unroll
        for (int off = 1; off < 32; off <<= 1) {
            int u = __shfl_up_sync(0xffffffffu, c, off);
            if (lane >= off) c += u;
        }
        ccur[lane] = c - ccnt[lane];
    }
    __syncthreads();
    if (tid < NUM_TASKS) {
        int pos = atomicAdd(&ccur[cls], 1);
        g_order[pos] = tid;
    }
}

// ---------------------------------------------------------------------------
// One W1 streaming pass for R rows via TMA bulk ring.
// Chunk c = 8KB = 4 stripes (stripe i = 128 float4 = f-group 4i..4i+3).
// Thread tid reads ring[s][j][tid]; warp p handles f = 16c + 4j + p.
// Pipeline: 3 chunks in flight; per-chunk __syncthreads makes slot reuse
// safe (slot of chunk c+3 was consumed by ALL threads at iteration c-1).
// 16 chunks/pass = 4 uses/slot => mbarrier parity returns to 0 every pass.
// NOTE: red aliases ring slots 0-1; only live in epilogue when no chunk is
// pending, and next pass's TMA issues happen after the epilogue barrier.
// ---------------------------------------------------------------------------
template<int R>
__device__ __forceinline__
void stream_pass(const char* __restrict__ Wb,
                 const float* __restrict__ x,
                 const float* __restrict__ b1s,
                 const float* __restrict__ w2s,
                 float b2,
                 float4 (*ring)[4][128],
                 float (*xs)[N_FEAT],
                 float (*red)[RCMAX][HID],
                 uint32_t mb0,
                 const int* __restrict__ rowp,
                 int nr,
                 float* __restrict__ out,
                 int tid, int q, int p) {
    // prologue: fire chunks 0..2 (stream in flight during x gather + barrier)
    if (tid == 0) {
        #pragma unroll
        for (int c = 0; c < NSLOT - 1; ++c) {
            uint32_t mb = mb0 + 8u * c;
            mbar_expect_tx(mb, CHUNK_B);
            uint32_t dst = (uint32_t)__cvta_generic_to_shared(&ring[c][0][0]);
            bulk_g2s(dst, Wb + (size_t)c * CHUNK_B, CHUNK_B, mb);
        }
    }

    // stage x rows into smem (zero-fill unused rows)
    #pragma unroll
    for (int r = 0; r < R; ++r) {
        float v0 = 0.f, v1 = 0.f;
        if (r < nr) {
            int row = rowp[r];
            v0 = x[(size_t)row * N_FEAT + tid];
            v1 = x[(size_t)row * N_FEAT + 128 + tid];
        }
        xs[r][tid]       = v0;
        xs[r][128 + tid] = v1;
    }
    __syncthreads();

    float4 acc[R];
    #pragma unroll
    for (int r = 0; r < R; ++r) acc[r] = make_float4(0.f, 0.f, 0.f, 0.f);

    // consume 16 chunks; issue chunk c+3 after the barrier of chunk c
    for (int c = 0; c < NCHUNK; ++c) {
        int s = c & (NSLOT - 1);
        mbar_wait(mb0 + 8u * s, (uint32_t)((c >> 2) & 1));
        #pragma unroll
        for (int j = 0; j < 4; ++j) {
            float4 w4 = ring[s][j][tid];
            int f = 16 * c + 4 * j + p;
            #pragma unroll
            for (int r = 0; r < R; ++r) {
                float xv = xs[r][f];          // warp-uniform smem broadcast
                acc[r].x = fmaf(xv, w4.x, acc[r].x);
                acc[r].y = fmaf(xv, w4.y, acc[r].y);
                acc[r].z = fmaf(xv, w4.z, acc[r].z);
                acc[r].w = fmaf(xv, w4.w, acc[r].w);
            }
        }
        __syncthreads();   // all threads done with chunk c (and c-1's slot)
        if (tid == 0 && c + (NSLOT - 1) < NCHUNK) {
            int nc = c + (NSLOT - 1);
            int ns = nc & (NSLOT - 1);
            uint32_t mb = mb0 + 8u * ns;
            mbar_expect_tx(mb, CHUNK_B);
            uint32_t dst = (uint32_t)__cvta_generic_to_shared(&ring[ns][0][0]);
            bulk_g2s(dst, Wb + (size_t)nc * CHUNK_B, CHUNK_B, mb);
        }
    }

    // cross-phase reduction staging (red aliases ring slots 0-1; all chunks
    // consumed, none pending)
    #pragma unroll
    for (int r = 0; r < R; ++r)
        ((float4*)&red[p][r][0])[q] = acc[r];
    __syncthreads();

    // epilogue: warp p handles rows p, p+4, ...; lane q strides H by 32
    for (int rr = p; rr < nr; rr += 4) {
        float part = 0.f;
        #pragma unroll
        for (int hh = q; hh < HID; hh += 32) {
            float s = red[0][rr][hh] + red[1][rr][hh] +
                      red[2][rr][hh] + red[3][rr][hh] + b1s[hh];
            // exact-erf GELU
            float g = 0.5f * s * (1.0f + erff(s * 0.70710678118654752f));
            part = fmaf(g, w2s[hh], part);
        }
        #pragma unroll
        for (int off = 16; off > 0; off >>= 1)
            part += __shfl_down_sync(0xffffffffu, part, off);
        if (q == 0)
            out[rowp[rr]] = part + b2;
    }
    __syncthreads();   // protect xs/red before next pass's TMA overwrites
}

// ---------------------------------------------------------------------------
// Main: persistent CTAs pull tasks (descending size) from a global cursor.
// 5 CTAs/SM; ~41KB smem/CTA (ring 32KB + xs 8KB + misc; red aliases ring).
// ---------------------------------------------------------------------------
__global__ __launch_bounds__(128, 5)
void main_kernel(const float* __restrict__ x,
                 const float* __restrict__ l1_emb,
                 const float* __restrict__ l1_bias,
                 const float* __restrict__ l2_emb,
                 const float* __restrict__ l2_bias,
                 float* __restrict__ out) {
    __shared__ __align__(128) float4 ring[NSLOT][4][128];   // 32 KB TMA ring
    __shared__ float xs[RCMAX][N_FEAT];                     // 8 KB
    __shared__ float b1s[HID], w2s[HID];
    __shared__ __align__(8) uint64_t mbar[NSLOT];
    __shared__ int s_idx;

    // red overlays ring slots 0-1 (16 KB); disjoint in time from chunk data
    float (*red)[RCMAX][HID] = (float (*)[RCMAX][HID])(&ring[0][0][0]);

    int tid = threadIdx.x;
    int q = tid & 31;
    int p = tid >> 5;

    uint32_t mb0 = (uint32_t)__cvta_generic_to_shared(&mbar[0]);
    if (tid == 0) {
        #pragma unroll
        for (int s = 0; s < NSLOT; ++s) mbar_init(mb0 + 8u * s, 1);
        asm volatile("fence.proxy.async.shared::cta;" ::: "memory");
    }
    __syncthreads();

    for (;;) {
        if (tid == 0) s_idx = atomicAdd(&g_cursor, 1);
        __syncthreads();
        int idx = s_idx;
        __syncthreads();
        if (idx >= NUM_TASKS) break;

        int t = g_order[idx];
        int start = g_offs[t];
        int n     = g_offs[t + 1] - start;
        if (n == 0) continue;

        b1s[tid] = l1_bias[t * HID + tid];
        w2s[tid] = l2_emb[t * HID + tid];
        float b2 = l2_bias[t];
        __syncthreads();

        const char* Wb = (const char*)(l1_emb + (size_t)t * (N_FEAT * HID));

        for (int r0 = 0; r0 < n; r0 += RCMAX) {
            int nr = min(RCMAX, n - r0);
            const int* rowp = g_rows + start + r0;
            if (nr <= 1)
                stream_pass<1>(Wb, x, b1s, w2s, b2, ring, xs, red, mb0, rowp, nr, out, tid, q, p);
            else if (nr <= 2)
                stream_pass<2>(Wb, x, b1s, w2s, b2, ring, xs, red, mb0, rowp, nr, out, tid, q, p);
            else if (nr <= 4)
                stream_pass<4>(Wb, x, b1s, w2s, b2, ring, xs, red, mb0, rowp, nr, out, tid, q, p);
            else
                stream_pass<8>(Wb, x, b1s, w2s, b2, ring, xs, red, mb0, rowp, nr, out, tid, q, p);
        }
    }
}

extern "C" void kernel_launch(void* const* d_in, const int* in_sizes, int n_in,
                              void* d_out, int out_size) {
    const float* x        = (const float*)d_in[0];
    const int*   task_ids = (const int*)  d_in[1];
    const float* l1_emb   = (const float*)d_in[2];
    const float* l1_bias  = (const float*)d_in[3];
    const float* l2_emb   = (const float*)d_in[4];
    const float* l2_bias  = (const float*)d_in[5];
    float* out = (float*)d_out;

    int batch = in_sizes[1];   // 4096

    setup_kernel<<<1, 1024>>>(task_ids, batch);
    main_kernel<<<5 * 148, 128>>>(x, l1_emb, l1_bias, l2_emb, l2_bias, out);
}